// round 11
// baseline (speedup 1.0000x reference)
#include <cuda_runtime.h>
#include <cuda_fp16.h>
#include <cstdint>
#include <cstddef>

// Problem constants
#define Bv   32
#define Nv   1025
#define DIMv 768
#define Hv   12
#define Dv   64
#define M1   (Bv * Nv)          // 32800 tokens
#define G3   (3 * Hv * Dv)      // 2304
#define BH   (Bv * Hv)          // 384
#define NP   1056               // n padded to mult of 32

// -------- scratch (device globals; zero-initialized at load; pads of vt/kft/
//          ctxh are NEVER written and must stay zero — do not memset) --------
__device__ __half g_xh  [(size_t)M1 * DIMv];
__device__ __half g_wqh [(size_t)G3 * DIMv];
__device__ __half g_woh [(size_t)DIMv * DIMv];
__device__ __half g_projh[(size_t)Dv * Dv];             // proj * 64^-0.25
__device__ __half g_qh  [(size_t)BH * Nv * Dv];         // roped q (bh,n,d)
__device__ __half g_kh  [(size_t)BH * Nv * Dv];         // roped k
__device__ __half g_vtmp[(size_t)BH * Nv * Dv];         // v (bh,n,d)
__device__ __half g_vt  [(size_t)BH * 72 * NP];         // v^T (bh,d,n); row64=ones
__device__ __half g_qfh [(size_t)BH * Nv * Dv];         // feature(q) (bh,n,j)
__device__ __half g_kft [(size_t)BH * Dv * NP];         // feature(k)^T (bh,j,n)
__device__ __half g_ctxh[(size_t)BH * 128 * Dv];        // rows0-63 ctx, row64 ksum
__device__ __half g_ah  [(size_t)M1 * DIMv];            // attn out fp16

// ============================================================================
// PTX helpers
// ============================================================================
__device__ __forceinline__ uint32_t s2u(const void* p) {
    uint32_t a;
    asm("{ .reg .u64 t; cvta.to.shared.u64 t, %1; cvt.u32.u64 %0, t; }"
        : "=r"(a) : "l"(p));
    return a;
}
__device__ __forceinline__ void cp16(uint32_t dst, const void* src) {
    asm volatile("cp.async.cg.shared.global [%0], [%1], 16;"
                 :: "r"(dst), "l"(src) : "memory");
}
__device__ __forceinline__ void cp16p(uint32_t dst, const void* src, int p) {
    asm volatile("cp.async.cg.shared.global [%0], [%1], 16, %2;"
                 :: "r"(dst), "l"(src), "r"(p) : "memory");
}
#define CPCOMMIT() asm volatile("cp.async.commit_group;" ::: "memory")
__device__ __forceinline__ void cpwait(int n) {
    if (n >= 2)      asm volatile("cp.async.wait_group 2;" ::: "memory");
    else if (n == 1) asm volatile("cp.async.wait_group 1;" ::: "memory");
    else             asm volatile("cp.async.wait_group 0;" ::: "memory");
}
__device__ __forceinline__ void ldm4(uint32_t* r, uint32_t a) {
    asm volatile("ldmatrix.sync.aligned.m8n8.x4.shared.b16 {%0,%1,%2,%3}, [%4];"
                 : "=r"(r[0]), "=r"(r[1]), "=r"(r[2]), "=r"(r[3]) : "r"(a));
}
__device__ __forceinline__ void ldm2(uint32_t* r, uint32_t a) {
    asm volatile("ldmatrix.sync.aligned.m8n8.x2.shared.b16 {%0,%1}, [%2];"
                 : "=r"(r[0]), "=r"(r[1]) : "r"(a));
}
__device__ __forceinline__ void mma16816(float* d, const uint32_t* a,
                                         const uint32_t* b) {
    asm volatile(
        "mma.sync.aligned.m16n8k16.row.col.f32.f16.f16.f32 "
        "{%0,%1,%2,%3},{%4,%5,%6,%7},{%8,%9},{%0,%1,%2,%3};"
        : "+f"(d[0]), "+f"(d[1]), "+f"(d[2]), "+f"(d[3])
        : "r"(a[0]), "r"(a[1]), "r"(a[2]), "r"(a[3]), "r"(b[0]), "r"(b[1]));
}
__device__ __forceinline__ void mma2(float* d, const uint32_t* a,
                                     uint32_t b0, uint32_t b1) {
    asm volatile(
        "mma.sync.aligned.m16n8k16.row.col.f32.f16.f16.f32 "
        "{%0,%1,%2,%3},{%4,%5,%6,%7},{%8,%9},{%0,%1,%2,%3};"
        : "+f"(d[0]), "+f"(d[1]), "+f"(d[2]), "+f"(d[3])
        : "r"(a[0]), "r"(a[1]), "r"(a[2]), "r"(a[3]), "r"(b0), "r"(b1));
}

// 16B-chunk layouts (conflict-free both sides; proven R5-R10)
__device__ __forceinline__ uint32_t chunk_off(int s, int r) {      // 128-row, legacy
    return (uint32_t)(((s << 7) + (r ^ (s << 1))) << 4);
}
__device__ __forceinline__ uint32_t chunk_off64(int s, int r) {    // 64-row, legacy
    return (uint32_t)(((s << 6) + (r ^ (s << 1))) << 4);
}
__device__ __forceinline__ uint32_t chunk_off8(int s, int r) {     // 128-row, BK=64
    return (uint32_t)(((s << 7) + (r ^ s)) << 4);
}

// ============================================================================
// conversions
// ============================================================================
__global__ __launch_bounds__(256)
void conv_fp16(const float* __restrict__ s, __half* __restrict__ h, size_t n4) {
    size_t i = (size_t)blockIdx.x * blockDim.x + threadIdx.x;
    size_t stride = (size_t)gridDim.x * blockDim.x;
    for (; i < n4; i += stride) {
        float4 v = reinterpret_cast<const float4*>(s)[i];
        reinterpret_cast<__half2*>(h)[2 * i]     = __floats2half2_rn(v.x, v.y);
        reinterpret_cast<__half2*>(h)[2 * i + 1] = __floats2half2_rn(v.z, v.w);
    }
}
__global__ __launch_bounds__(256)
void conv_proj(const float* __restrict__ p, __half* __restrict__ ph) {
    int i = blockIdx.x * 256 + threadIdx.x;
    if (i < Dv * Dv) ph[i] = __float2half_rn(p[i] * 0.35355339059327379f);
}

// ============================================================================
// Big GEMM core: CTA 128x128, FOUR warps (128 thr), warp tile 64x64, BK=64,
// 3-stage cp.async (32KB/stage), 2 CTAs/SM.  Fragment bytes/chunk: 64KB
// (vs 96KB @ 8-warp 64x32) — smem-crossbar-bound model, R10 post-mortem.
// Warp-level fragment mapping identical to R9's gemm_big (proven bit-exact).
// ============================================================================
#define BKi     64
#define PLANE_B 16384
#define STAGE_B (2 * PLANE_B)
#define NSTAGE  3
#define GSMEM   (NSTAGE * STAGE_B)

// ============================================================================
// GEMM1 fused: qkv = xh @ wqh^T, RoPE in epilogue -> qh/kh/vtmp fp16
// grid (18, 257), 128 threads.
// ============================================================================
__global__ __launch_bounds__(128, 2)
void gemm_qkv(const __half* __restrict__ Ah, const __half* __restrict__ Bh,
              const float* __restrict__ fcos, const float* __restrict__ fsin,
              __half* __restrict__ qh, __half* __restrict__ kh,
              __half* __restrict__ vtmp) {
    extern __shared__ char dsm[];
    const uint32_t base = s2u(dsm);
    const int tid  = threadIdx.x;
    const int warp = tid >> 5, lane = tid & 31;
    const int row0 = blockIdx.y * 128, col0 = blockIdx.x * 128;
    const int wm = (warp >> 1) * 64, wn = (warp & 1) * 64;
    const int K = DIMv, nk = K / BKi;   // 12

    float acc[4][8][4];
    #pragma unroll
    for (int i = 0; i < 4; ++i)
        #pragma unroll
        for (int j = 0; j < 8; ++j)
            #pragma unroll
            for (int c = 0; c < 4; ++c) acc[i][j][c] = 0.f;

    // stage one 64-k chunk: A 1024 + B 1024 chunks, 128 threads -> 16 each
    auto stage = [&](int t, int sb) {
        const int k0 = t * BKi;
        const uint32_t sbase = base + sb * STAGE_B;
        #pragma unroll
        for (int l = 0; l < 16; ++l) {
            int idx = tid + l * 128;
            int p = idx >> 10, cid = idx & 1023;
            int r = cid >> 3, s = cid & 7;
            uint32_t dst = sbase + p * PLANE_B + chunk_off8(s, r);
            if (p == 0) {
                int gr = row0 + r, ok = (gr < M1);
                cp16p(dst, Ah + (size_t)(ok ? gr : 0) * K + k0 + s * 8, ok ? 16 : 0);
            } else {
                cp16(dst, Bh + (size_t)(col0 + r) * K + k0 + s * 8);
            }
        }
    };

    stage(0, 0); CPCOMMIT();
    stage(1, 1); CPCOMMIT();

    const int a_r = lane & 15, a_s = lane >> 4;

    for (int t = 0; t < nk; ++t) {
        cpwait(min(nk - 1 - t, 1));
        __syncthreads();
        const uint32_t pb = base + (t % NSTAGE) * STAGE_B;
        #pragma unroll
        for (int ks = 0; ks < 4; ++ks) {
            uint32_t af[4][4], bf[4][4];
            #pragma unroll
            for (int nj = 0; nj < 4; ++nj)
                ldm4(bf[nj], pb + PLANE_B + chunk_off8(2 * ks + a_s, wn + nj * 16 + a_r));
            #pragma unroll
            for (int mi = 0; mi < 4; ++mi)
                ldm4(af[mi], pb + chunk_off8(2 * ks + a_s, wm + mi * 16 + a_r));
            #pragma unroll
            for (int mi = 0; mi < 4; ++mi)
                #pragma unroll
                for (int nj = 0; nj < 4; ++nj) {
                    mma2(acc[mi][2 * nj],     af[mi], bf[nj][0], bf[nj][2]);
                    mma2(acc[mi][2 * nj + 1], af[mi], bf[nj][1], bf[nj][3]);
                }
        }
        if (t + 2 < nk) { stage(t + 2, (t + 2) % NSTAGE); CPCOMMIT(); }
    }

    // ---- fused epilogue: RoPE + fp16 scatter ----
    const int er = lane >> 2, ec = 2 * (lane & 3);
    const int part = col0 / DIMv;              // col tile entirely in one part
    __half* dstbase = (part == 0) ? qh : (part == 1) ? kh : vtmp;

    int rb[8], rn[8];
    #pragma unroll
    for (int mi = 0; mi < 4; ++mi) {
        int gr = row0 + wm + mi * 16 + er;
        rb[2 * mi] = gr / Nv; rn[2 * mi] = gr - rb[2 * mi] * Nv;
        gr += 8;
        rb[2 * mi + 1] = gr / Nv; rn[2 * mi + 1] = gr - rb[2 * mi + 1] * Nv;
    }

    #pragma unroll
    for (int mi = 0; mi < 4; ++mi)
        #pragma unroll
        for (int ni = 0; ni < 8; ++ni) {
            int gc = col0 + wn + ni * 8 + ec;
            int rem = gc - part * DIMv;
            int h = rem >> 6, d = rem & 63, i = d >> 1;
            #pragma unroll
            for (int hf = 0; hf < 2; ++hf) {
                int gr = row0 + wm + mi * 16 + er + 8 * hf;
                if (gr >= M1) continue;
                int b = rb[2 * mi + hf], n = rn[2 * mi + hf];
                float v0 = acc[mi][ni][2 * hf], v1 = acc[mi][ni][2 * hf + 1];
                if (part < 2 && n > 0) {
                    float c = __ldg(&fcos[(size_t)(n - 1) * 32 + i]);
                    float s = __ldg(&fsin[(size_t)(n - 1) * 32 + i]);
                    float t0 = v0 * c - v1 * s;
                    v1 = v0 * s + v1 * c;
                    v0 = t0;
                }
                *reinterpret_cast<__half2*>(
                    &dstbase[(((size_t)b * Hv + h) * Nv + n) * Dv + d]) =
                    __floats2half2_rn(v0, v1);
            }
        }
}

// ============================================================================
// GEMM2 (generic): C = A @ B^T + bias, fp32 out. Same 4-warp core.
// ============================================================================
__global__ __launch_bounds__(128, 2)
void gemm_out(const __half* __restrict__ Ah, const __half* __restrict__ Bh,
              const float* __restrict__ bias, float* __restrict__ C,
              int M, int Nc, int K) {
    extern __shared__ char dsm[];
    const uint32_t base = s2u(dsm);
    const int tid  = threadIdx.x;
    const int warp = tid >> 5, lane = tid & 31;
    const int row0 = blockIdx.y * 128, col0 = blockIdx.x * 128;
    const int wm = (warp >> 1) * 64, wn = (warp & 1) * 64;
    const int nk = K / BKi;

    float acc[4][8][4];
    #pragma unroll
    for (int i = 0; i < 4; ++i)
        #pragma unroll
        for (int j = 0; j < 8; ++j)
            #pragma unroll
            for (int c = 0; c < 4; ++c) acc[i][j][c] = 0.f;

    auto stage = [&](int t, int sb) {
        const int k0 = t * BKi;
        const uint32_t sbase = base + sb * STAGE_B;
        #pragma unroll
        for (int l = 0; l < 16; ++l) {
            int idx = tid + l * 128;
            int p = idx >> 10, cid = idx & 1023;
            int r = cid >> 3, s = cid & 7;
            uint32_t dst = sbase + p * PLANE_B + chunk_off8(s, r);
            if (p == 0) {
                int gr = row0 + r, ok = (gr < M);
                cp16p(dst, Ah + (size_t)(ok ? gr : 0) * K + k0 + s * 8, ok ? 16 : 0);
            } else {
                cp16(dst, Bh + (size_t)(col0 + r) * K + k0 + s * 8);
            }
        }
    };

    stage(0, 0); CPCOMMIT();
    stage(1, 1); CPCOMMIT();

    const int a_r = lane & 15, a_s = lane >> 4;

    for (int t = 0; t < nk; ++t) {
        cpwait(min(nk - 1 - t, 1));
        __syncthreads();
        const uint32_t pb = base + (t % NSTAGE) * STAGE_B;
        #pragma unroll
        for (int ks = 0; ks < 4; ++ks) {
            uint32_t af[4][4], bf[4][4];
            #pragma unroll
            for (int nj = 0; nj < 4; ++nj)
                ldm4(bf[nj], pb + PLANE_B + chunk_off8(2 * ks + a_s, wn + nj * 16 + a_r));
            #pragma unroll
            for (int mi = 0; mi < 4; ++mi)
                ldm4(af[mi], pb + chunk_off8(2 * ks + a_s, wm + mi * 16 + a_r));
            #pragma unroll
            for (int mi = 0; mi < 4; ++mi)
                #pragma unroll
                for (int nj = 0; nj < 4; ++nj) {
                    mma2(acc[mi][2 * nj],     af[mi], bf[nj][0], bf[nj][2]);
                    mma2(acc[mi][2 * nj + 1], af[mi], bf[nj][1], bf[nj][3]);
                }
        }
        if (t + 2 < nk) { stage(t + 2, (t + 2) % NSTAGE); CPCOMMIT(); }
    }

    const int er = lane >> 2, ec = 2 * (lane & 3);
    #pragma unroll
    for (int mi = 0; mi < 4; ++mi)
        #pragma unroll
        for (int ni = 0; ni < 8; ++ni) {
            int gc = col0 + wn + ni * 8 + ec;
            float b0 = bias[gc], b1 = bias[gc + 1];
            int gr0 = row0 + wm + mi * 16 + er;
            if (gr0 < M)
                *reinterpret_cast<float2*>(&C[(size_t)gr0 * Nc + gc]) =
                    make_float2(acc[mi][ni][0] + b0, acc[mi][ni][1] + b1);
            if (gr0 + 8 < M)
                *reinterpret_cast<float2*>(&C[(size_t)(gr0 + 8) * Nc + gc]) =
                    make_float2(acc[mi][ni][2] + b0, acc[mi][ni][3] + b1);
        }
}

// ============================================================================
// v transpose: vtmp (bh,n,d) -> vt (bh,d,n) + ones row 64.  grid (33, 384).
// ============================================================================
__global__ __launch_bounds__(256)
void vtrans(const __half* __restrict__ vtmp, __half* __restrict__ vt) {
    __shared__ __half sv[64 * 40];
    const int tid = threadIdx.x;
    const int n0 = blockIdx.x * 32, bh = blockIdx.y;

    int nl = tid >> 3, seg = (tid & 7) * 8;
    int n = n0 + nl;
    __half tmp[8];
    if (n < Nv) {
        *reinterpret_cast<uint4*>(tmp) = *reinterpret_cast<const uint4*>(
            &vtmp[((size_t)bh * Nv + n) * Dv + seg]);
    } else {
        #pragma unroll
        for (int j = 0; j < 8; ++j) tmp[j] = __float2half(0.f);
    }
    #pragma unroll
    for (int j = 0; j < 8; ++j) sv[(seg + j) * 40 + nl] = tmp[j];
    __syncthreads();

    int d = tid >> 2, sg = (tid & 3) * 8;
    int nb = n0 + sg;
    __half* dst = &vt[(size_t)bh * 72 * NP + (size_t)d * NP + nb];
    if (nb + 7 < Nv) {
        *reinterpret_cast<uint4*>(dst) = *reinterpret_cast<uint4*>(&sv[d * 40 + sg]);
    } else {
        for (int j = 0; j < 8; ++j)
            if (nb + j < Nv) dst[j] = sv[d * 40 + sg + j];
    }
    if (tid < 32 && n0 + tid < Nv)
        vt[(size_t)bh * 72 * NP + (size_t)64 * NP + n0 + tid] = __float2half(1.f);
}

// ============================================================================
// feature GEMM: F = relu(X @ projS^T) + 1e-6
// grid (9, 384, 2): z=0 -> qf (n,j); z=1 -> kfT (j,n)
// ============================================================================
__global__ __launch_bounds__(256)
void feat_gemm(const __half* __restrict__ qh, const __half* __restrict__ kh,
               const __half* __restrict__ projS,
               __half* __restrict__ qf, __half* __restrict__ kft) {
    __shared__ char fsm[24576];
    const uint32_t base = s2u(fsm), bB = base + 16384;
    const int tid = threadIdx.x, warp = tid >> 5, lane = tid & 31;
    const int n0 = blockIdx.x * 128, bh = blockIdx.y, qk = blockIdx.z;
    const __half* A = (qk ? kh : qh) + (size_t)bh * Nv * Dv;

    #pragma unroll
    for (int l = 0; l < 4; ++l) {
        int idx = tid + l * 256;
        int r = idx >> 3, s = idx & 7;
        int n = n0 + r, ok = (n < Nv);
        cp16p(base + chunk_off(s, r), A + (size_t)(ok ? n : 0) * Dv + s * 8, ok ? 16 : 0);
    }
    #pragma unroll
    for (int l = 0; l < 2; ++l) {
        int idx = tid + l * 256;
        int r = idx >> 3, s = idx & 7;
        cp16(bB + chunk_off64(s, r), projS + (size_t)r * Dv + s * 8);
    }
    CPCOMMIT(); cpwait(0); __syncthreads();

    const int wm = (warp >> 1) * 32, wn = (warp & 1) * 32;
    const int a_r = lane & 15, a_s = lane >> 4;
    const int b_r = lane & 7,  b_s = (lane >> 3) & 1;
    float acc[2][4][4];
    #pragma unroll
    for (int i = 0; i < 2; ++i)
        #pragma unroll
        for (int j = 0; j < 4; ++j)
            #pragma unroll
            for (int c = 0; c < 4; ++c) acc[i][j][c] = 0.f;

    #pragma unroll
    for (int ks = 0; ks < 4; ++ks) {
        uint32_t af[2][4], bf[4][2];
        #pragma unroll
        for (int ni = 0; ni < 4; ++ni)
            ldm2(bf[ni], bB + chunk_off64(2 * ks + b_s, wn + ni * 8 + b_r));
        #pragma unroll
        for (int mi = 0; mi < 2; ++mi)
            ldm4(af[mi], base + chunk_off(2 * ks + a_s, wm + mi * 16 + a_r));
        #pragma unroll
        for (int mi = 0; mi < 2; ++mi)
            #pragma unroll
            for (int ni = 0; ni < 4; ++ni)
                mma16816(acc[mi][ni], af[mi], bf[ni]);
    }

    const int er = lane >> 2, ec = 2 * (lane & 3);
    if (qk == 0) {
        #pragma unroll
        for (int mi = 0; mi < 2; ++mi)
            #pragma unroll
            for (int ni = 0; ni < 4; ++ni) {
                int row = wm + mi * 16 + er, col = wn + ni * 8 + ec;
                int n = n0 + row;
                if (n < Nv) {
                    float v0 = fmaxf(acc[mi][ni][0], 0.f) + 1e-6f;
                    float v1 = fmaxf(acc[mi][ni][1], 0.f) + 1e-6f;
                    *reinterpret_cast<__half2*>(
                        &qf[((size_t)bh * Nv + n) * Dv + col]) = __floats2half2_rn(v0, v1);
                }
                if (n + 8 < Nv) {
                    float v2 = fmaxf(acc[mi][ni][2], 0.f) + 1e-6f;
                    float v3 = fmaxf(acc[mi][ni][3], 0.f) + 1e-6f;
                    *reinterpret_cast<__half2*>(
                        &qf[((size_t)bh * Nv + n + 8) * Dv + col]) = __floats2half2_rn(v2, v3);
                }
            }
    } else {
        __syncthreads();
        __half* sm16 = reinterpret_cast<__half*>(fsm);
        #pragma unroll
        for (int mi = 0; mi < 2; ++mi)
            #pragma unroll
            for (int ni = 0; ni < 4; ++ni) {
                int row = wm + mi * 16 + er, col = wn + ni * 8 + ec;
                sm16[(col)     * 136 + row    ] = __float2half_rn(fmaxf(acc[mi][ni][0], 0.f) + 1e-6f);
                sm16[(col + 1) * 136 + row    ] = __float2half_rn(fmaxf(acc[mi][ni][1], 0.f) + 1e-6f);
                sm16[(col)     * 136 + row + 8] = __float2half_rn(fmaxf(acc[mi][ni][2], 0.f) + 1e-6f);
                sm16[(col + 1) * 136 + row + 8] = __float2half_rn(fmaxf(acc[mi][ni][3], 0.f) + 1e-6f);
            }
        __syncthreads();
        int j = tid >> 2, seg = (tid & 3) * 32;
        __half* dst = &kft[(size_t)bh * Dv * NP + (size_t)j * NP + n0 + seg];
        #pragma unroll
        for (int i = 0; i < 32; i += 2) {
            int n = n0 + seg + i;
            if (n + 1 < Nv)
                *reinterpret_cast<__half2*>(dst + i) =
                    *reinterpret_cast<const __half2*>(&sm16[j * 136 + seg + i]);
            else if (n < Nv)
                dst[i] = sm16[j * 136 + seg + i];
        }
    }
}

// ============================================================================
// ctx GEMM: C[r][d] = sum_n vt[r,n]*kfT[d,n]; row 64 = ksum.
// ============================================================================
#define CSTG_B 12288
__global__ __launch_bounds__(256)
void ctx_gemm(const __half* __restrict__ vt, const __half* __restrict__ kft,
              __half* __restrict__ ctxh) {
    __shared__ char csm[4 * CSTG_B];
    const uint32_t base = s2u(csm);
    const int tid = threadIdx.x, warp = tid >> 5, lane = tid & 31;
    const int bh = blockIdx.x;
    const __half* Av = vt  + (size_t)bh * 72 * NP;
    const __half* Bk = kft + (size_t)bh * Dv * NP;
    const int nk = NP / 32;

    auto stage = [&](int t, int sb) {
        const int k0 = t * 32;
        const uint32_t sbase = base + sb * CSTG_B;
        #pragma unroll
        for (int l = 0; l < 3; ++l) {
            int idx = tid + l * 256;
            if (idx < 512) {
                int r = idx >> 2, s = idx & 3;
                int ok = (r < 72);
                cp16p(sbase + chunk_off(s, r),
                      Av + (size_t)(ok ? r : 0) * NP + k0 + s * 8, ok ? 16 : 0);
            } else {
                int j = idx - 512;
                int r = j >> 2, s = j & 3;
                cp16(sbase + 8192 + chunk_off64(s, r),
                     Bk + (size_t)r * NP + k0 + s * 8);
            }
        }
    };

    stage(0, 0); CPCOMMIT();
    stage(1, 1); CPCOMMIT();
    stage(2, 2); CPCOMMIT();

    const int wm = (warp >> 1) * 32, wn = (warp & 1) * 32;
    const int a_r = lane & 15, a_s = lane >> 4;
    const int b_r = lane & 7,  b_s = (lane >> 3) & 1;
    float acc[2][4][4];
    #pragma unroll
    for (int i = 0; i < 2; ++i)
        #pragma unroll
        for (int j = 0; j < 4; ++j)
            #pragma unroll
            for (int c = 0; c < 4; ++c) acc[i][j][c] = 0.f;

    for (int t = 0; t < nk; ++t) {
        cpwait(min(nk - 1 - t, 2));
        __syncthreads();
        const uint32_t pb = base + (t & 3) * CSTG_B;
        #pragma unroll
        for (int ks = 0; ks < 2; ++ks) {
            uint32_t af[2][4], bf[4][2];
            #pragma unroll
            for (int ni = 0; ni < 4; ++ni)
                ldm2(bf[ni], pb + 8192 + chunk_off64(2 * ks + b_s, wn + ni * 8 + b_r));
            #pragma unroll
            for (int mi = 0; mi < 2; ++mi)
                ldm4(af[mi], pb + chunk_off(2 * ks + a_s, wm + mi * 16 + a_r));
            #pragma unroll
            for (int mi = 0; mi < 2; ++mi)
                #pragma unroll
                for (int ni = 0; ni < 4; ++ni)
                    mma16816(acc[mi][ni], af[mi], bf[ni]);
        }
        __syncthreads();
        if (t + 3 < nk) { stage(t + 3, (t + 3) & 3); CPCOMMIT(); }
    }

    const int er = lane >> 2, ec = 2 * (lane & 3);
    #pragma unroll
    for (int mi = 0; mi < 2; ++mi)
        #pragma unroll
        for (int ni = 0; ni < 4; ++ni) {
            int row = wm + mi * 16 + er, col = wn + ni * 8 + ec;
            if (row < 72)
                *reinterpret_cast<__half2*>(&ctxh[(size_t)bh * 128 * Dv + row * Dv + col]) =
                    __floats2half2_rn(acc[mi][ni][0], acc[mi][ni][1]);
            if (row + 8 < 72)
                *reinterpret_cast<__half2*>(&ctxh[(size_t)bh * 128 * Dv + (row + 8) * Dv + col]) =
                    __floats2half2_rn(acc[mi][ni][2], acc[mi][ni][3]);
        }
}

// ============================================================================
// out GEMM: col64 = denom; divide in epilogue -> ah fp16
// ============================================================================
__global__ __launch_bounds__(256)
void out_gemm(const __half* __restrict__ qf, const __half* __restrict__ ctxh,
              __half* __restrict__ ah) {
    __shared__ char osm[32768];
    __shared__ float sden[128];
    const uint32_t base = s2u(osm), bB = base + 16384;
    const int tid = threadIdx.x, warp = tid >> 5, lane = tid & 31;
    const int n0 = blockIdx.x * 128, bh = blockIdx.y;
    const int b = bh / Hv, h = bh % Hv;
    const __half* A = qf   + (size_t)bh * Nv * Dv;
    const __half* Bm = ctxh + (size_t)bh * 128 * Dv;

    #pragma unroll
    for (int l = 0; l < 4; ++l) {
        int idx = tid + l * 256;
        int r = idx >> 3, s = idx & 7;
        int n = n0 + r, ok = (n < Nv);
        cp16p(base + chunk_off(s, r), A + (size_t)(ok ? n : 0) * Dv + s * 8, ok ? 16 : 0);
    }
    #pragma unroll
    for (int l = 0; l < 4; ++l) {
        int idx = tid + l * 256;
        int r = idx >> 3, s = idx & 7;
        cp16(bB + chunk_off(s, r), Bm + (size_t)r * Dv + s * 8);
    }
    CPCOMMIT(); cpwait(0); __syncthreads();

    const int wm = (warp >> 2) * 64, wn = (warp & 3) * 32;
    const int a_r = lane & 15, a_s = lane >> 4;
    const int b_r = lane & 7,  b_s = (lane >> 3) & 1;
    float acc[4][4][4];
    #pragma unroll
    for (int i = 0; i < 4; ++i)
        #pragma unroll
        for (int j = 0; j < 4; ++j)
            #pragma unroll
            for (int c = 0; c < 4; ++c) acc[i][j][c] = 0.f;

    #pragma unroll
    for (int ks = 0; ks < 4; ++ks) {
        uint32_t af[4][4], bf[4][2];
        #pragma unroll
        for (int ni = 0; ni < 4; ++ni)
            ldm2(bf[ni], bB + chunk_off(2 * ks + b_s, wn + ni * 8 + b_r));
        #pragma unroll
        for (int mi = 0; mi < 4; ++mi)
            ldm4(af[mi], base + chunk_off(2 * ks + a_s, wm + mi * 16 + a_r));
        #pragma unroll
        for (int mi = 0; mi < 4; ++mi)
            #pragma unroll
            for (int ni = 0; ni < 4; ++ni)
                mma16816(acc[mi][ni], af[mi], bf[ni]);
    }

    const int er = lane >> 2, ec = 2 * (lane & 3);
    if (wn == 64 && (lane & 3) == 0) {
        #pragma unroll
        for (int mi = 0; mi < 4; ++mi) {
            sden[wm + mi * 16 + er]     = acc[mi][0][0];
            sden[wm + mi * 16 + er + 8] = acc[mi][0][2];
        }
    }
    __syncthreads();
    if (wn < 64) {
        #pragma unroll
        for (int mi = 0; mi < 4; ++mi)
            #pragma unroll
            for (int ni = 0; ni < 4; ++ni) {
                int row = wm + mi * 16 + er, col = wn + ni * 8 + ec;
                int n = n0 + row;
                if (n < Nv) {
                    float inv = 1.f / sden[row];
                    *reinterpret_cast<__half2*>(
                        &ah[((size_t)(b * Nv + n)) * DIMv + h * Dv + col]) =
                        __floats2half2_rn(acc[mi][ni][0] * inv, acc[mi][ni][1] * inv);
                }
                if (n + 8 < Nv) {
                    float inv = 1.f / sden[row + 8];
                    *reinterpret_cast<__half2*>(
                        &ah[((size_t)(b * Nv + n + 8)) * DIMv + h * Dv + col]) =
                        __floats2half2_rn(acc[mi][ni][2] * inv, acc[mi][ni][3] * inv);
                }
            }
    }
}

// ============================================================================
// launcher
// ============================================================================
extern "C" void kernel_launch(void* const* d_in, const int* in_sizes, int n_in,
                              void* d_out, int out_size) {
    const float* x     = (const float*)d_in[0];
    const float* W_qkv = (const float*)d_in[1];
    const float* W_out = (const float*)d_in[2];
    const float* b_out = (const float*)d_in[3];
    const float* proj  = (const float*)d_in[4];
    const float* fcos  = (const float*)d_in[5];
    const float* fsin  = (const float*)d_in[6];
    float* out = (float*)d_out;

    __half *xh, *wqh, *woh, *projh, *qh, *kh, *vtmp, *vt, *qfh, *kft, *ctxh, *ah;
    cudaGetSymbolAddress((void**)&xh,    g_xh);
    cudaGetSymbolAddress((void**)&wqh,   g_wqh);
    cudaGetSymbolAddress((void**)&woh,   g_woh);
    cudaGetSymbolAddress((void**)&projh, g_projh);
    cudaGetSymbolAddress((void**)&qh,    g_qh);
    cudaGetSymbolAddress((void**)&kh,    g_kh);
    cudaGetSymbolAddress((void**)&vtmp,  g_vtmp);
    cudaGetSymbolAddress((void**)&vt,    g_vt);
    cudaGetSymbolAddress((void**)&qfh,   g_qfh);
    cudaGetSymbolAddress((void**)&kft,   g_kft);
    cudaGetSymbolAddress((void**)&ctxh,  g_ctxh);
    cudaGetSymbolAddress((void**)&ah,    g_ah);

    cudaFuncSetAttribute(gemm_qkv,
                         cudaFuncAttributeMaxDynamicSharedMemorySize, GSMEM);
    cudaFuncSetAttribute(gemm_out,
                         cudaFuncAttributeMaxDynamicSharedMemorySize, GSMEM);

    // 0) conversions
    conv_fp16<<<2048, 256>>>(x,     xh,  (size_t)M1 * DIMv / 4);
    conv_fp16<<<512,  256>>>(W_qkv, wqh, (size_t)G3 * DIMv / 4);
    conv_fp16<<<256,  256>>>(W_out, woh, (size_t)DIMv * DIMv / 4);
    conv_proj<<<16,   256>>>(proj, projh);

    // 1) QKV projection with fused RoPE -> qh, kh, vtmp (fp16)
    {
        dim3 grid(G3 / 128, (M1 + 127) / 128);
        gemm_qkv<<<grid, 128, GSMEM>>>(xh, wqh, fcos, fsin, qh, kh, vtmp);
    }
    // 2) v transpose + ones row
    {
        dim3 grid(33, BH);
        vtrans<<<grid, 256>>>(vtmp, vt);
    }
    // 3) feature maps (HMMA)
    {
        dim3 grid(9, BH, 2);
        feat_gemm<<<grid, 256>>>(qh, kh, projh, qfh, kft);
    }
    // 4) context + ksum (HMMA, ones-row trick)
    ctx_gemm<<<BH, 256>>>(vt, kft, ctxh);
    // 5) output contraction + divide -> ah fp16
    {
        dim3 grid(9, BH);
        out_gemm<<<grid, 256>>>(qfh, ctxh, ah);
    }
    // 6) output projection + bias
    {
        dim3 grid(DIMv / 128, (M1 + 127) / 128);
        gemm_out<<<grid, 128, GSMEM>>>(ah, woh, b_out, out, M1, DIMv, DIMv);
    }
}

// round 12
// speedup vs baseline: 1.1541x; 1.1541x over previous
#include <cuda_runtime.h>
#include <cuda_fp16.h>
#include <cstdint>
#include <cstddef>

// Problem constants
#define Bv   32
#define Nv   1025
#define DIMv 768
#define Hv   12
#define Dv   64
#define M1   (Bv * Nv)          // 32800 tokens
#define G3   (3 * Hv * Dv)      // 2304
#define BH   (Bv * Hv)          // 384
#define NP   1056               // n padded to mult of 32

// -------- scratch (device globals; zero-initialized at load; pads of vt/kft/
//          ctxh are NEVER written and must stay zero — do not memset) --------
__device__ __half g_xh  [(size_t)M1 * DIMv];
__device__ __half g_wqh [(size_t)G3 * DIMv];
__device__ __half g_woh [(size_t)DIMv * DIMv];
__device__ __half g_projh[(size_t)Dv * Dv];             // proj * 64^-0.25
__device__ __half g_qh  [(size_t)BH * Nv * Dv];         // roped q (bh,n,d)
__device__ __half g_kh  [(size_t)BH * Nv * Dv];         // roped k
__device__ __half g_vt  [(size_t)BH * 72 * NP];         // v^T (bh,d,n); row64=ones
__device__ __half g_qfh [(size_t)BH * Nv * Dv];         // feature(q) (bh,n,j)
__device__ __half g_kft [(size_t)BH * Dv * NP];         // feature(k)^T (bh,j,n)
__device__ __half g_ctxh[(size_t)BH * 128 * Dv];        // rows0-63 ctx, row64 ksum
__device__ __half g_ah  [(size_t)M1 * DIMv];            // attn out fp16

// ============================================================================
// PTX helpers
// ============================================================================
__device__ __forceinline__ uint32_t s2u(const void* p) {
    uint32_t a;
    asm("{ .reg .u64 t; cvta.to.shared.u64 t, %1; cvt.u32.u64 %0, t; }"
        : "=r"(a) : "l"(p));
    return a;
}
__device__ __forceinline__ void cp16(uint32_t dst, const void* src) {
    asm volatile("cp.async.cg.shared.global [%0], [%1], 16;"
                 :: "r"(dst), "l"(src) : "memory");
}
__device__ __forceinline__ void cp16p(uint32_t dst, const void* src, int p) {
    asm volatile("cp.async.cg.shared.global [%0], [%1], 16, %2;"
                 :: "r"(dst), "l"(src), "r"(p) : "memory");
}
#define CPCOMMIT() asm volatile("cp.async.commit_group;" ::: "memory")
__device__ __forceinline__ void cpwait(int n) {
    if (n >= 2)      asm volatile("cp.async.wait_group 2;" ::: "memory");
    else if (n == 1) asm volatile("cp.async.wait_group 1;" ::: "memory");
    else             asm volatile("cp.async.wait_group 0;" ::: "memory");
}
__device__ __forceinline__ void ldm4(uint32_t* r, uint32_t a) {
    asm volatile("ldmatrix.sync.aligned.m8n8.x4.shared.b16 {%0,%1,%2,%3}, [%4];"
                 : "=r"(r[0]), "=r"(r[1]), "=r"(r[2]), "=r"(r[3]) : "r"(a));
}
__device__ __forceinline__ void ldm2(uint32_t* r, uint32_t a) {
    asm volatile("ldmatrix.sync.aligned.m8n8.x2.shared.b16 {%0,%1}, [%2];"
                 : "=r"(r[0]), "=r"(r[1]) : "r"(a));
}
__device__ __forceinline__ void mma16816(float* d, const uint32_t* a,
                                         const uint32_t* b) {
    asm volatile(
        "mma.sync.aligned.m16n8k16.row.col.f32.f16.f16.f32 "
        "{%0,%1,%2,%3},{%4,%5,%6,%7},{%8,%9},{%0,%1,%2,%3};"
        : "+f"(d[0]), "+f"(d[1]), "+f"(d[2]), "+f"(d[3])
        : "r"(a[0]), "r"(a[1]), "r"(a[2]), "r"(a[3]), "r"(b[0]), "r"(b[1]));
}

// 16B-chunk layouts (conflict-free both sides; proven R5-R11)
__device__ __forceinline__ uint32_t chunk_off(int s, int r) {      // 128-row, legacy
    return (uint32_t)(((s << 7) + (r ^ (s << 1))) << 4);
}
__device__ __forceinline__ uint32_t chunk_off64(int s, int r) {    // 64-row, legacy
    return (uint32_t)(((s << 6) + (r ^ (s << 1))) << 4);
}
__device__ __forceinline__ uint32_t chunk_off8(int s, int r) {     // 128-row, BK=64
    return (uint32_t)(((s << 7) + (r ^ s)) << 4);
}

// ============================================================================
// conversions
// ============================================================================
__global__ __launch_bounds__(256)
void conv_fp16(const float* __restrict__ s, __half* __restrict__ h, size_t n4) {
    size_t i = (size_t)blockIdx.x * blockDim.x + threadIdx.x;
    size_t stride = (size_t)gridDim.x * blockDim.x;
    for (; i < n4; i += stride) {
        float4 v = reinterpret_cast<const float4*>(s)[i];
        reinterpret_cast<__half2*>(h)[2 * i]     = __floats2half2_rn(v.x, v.y);
        reinterpret_cast<__half2*>(h)[2 * i + 1] = __floats2half2_rn(v.z, v.w);
    }
}
// proj scale + vt ones rows (replaces conv_proj and vtrans's ones write)
__global__ __launch_bounds__(256)
void conv_misc(const float* __restrict__ p, __half* __restrict__ ph,
               __half* __restrict__ vt) {
    int i = blockIdx.x * 256 + threadIdx.x;
    if (i < Dv * Dv) {
        ph[i] = __float2half_rn(p[i] * 0.35355339059327379f);
    }
    int j = i - Dv * Dv;
    if (j >= 0 && j < BH * Nv) {
        int bh = j / Nv, n = j - bh * Nv;
        vt[(size_t)bh * 72 * NP + (size_t)64 * NP + n] = __float2half(1.f);
    }
}

// ============================================================================
// GEMM core (R8-proven, FROZEN): CTA 128x128, 8 warps, warp 64x32, BK=64,
// 3-stage cp.async (32KB/stage), 2 CTAs/SM, ldm2-B fragments.
// ============================================================================
#define BKi     64
#define PLANE_B 16384
#define STAGE_B (2 * PLANE_B)
#define NSTAGE  3
#define GSMEM   (NSTAGE * STAGE_B)

// ============================================================================
// GEMM1 fused: qkv = xh @ wqh^T; RoPE epilogue -> qh/kh; v-part epilogue
// transposes in-CTA (feat_gemm kfT pattern) -> vt directly (no vtmp/vtrans).
// grid (18, 257), 256 threads.
// ============================================================================
__global__ __launch_bounds__(256, 2)
void gemm_qkv(const __half* __restrict__ Ah, const __half* __restrict__ Bh,
              const float* __restrict__ fcos, const float* __restrict__ fsin,
              __half* __restrict__ qh, __half* __restrict__ kh,
              __half* __restrict__ vt) {
    extern __shared__ char dsm[];
    const uint32_t base = s2u(dsm);
    const int tid  = threadIdx.x;
    const int warp = tid >> 5, lane = tid & 31;
    const int row0 = blockIdx.y * 128, col0 = blockIdx.x * 128;
    const int wm = (warp >> 2) * 64, wn = (warp & 3) * 32;
    const int K = DIMv, nk = K / BKi;   // 12

    float acc[4][4][4];
    #pragma unroll
    for (int i = 0; i < 4; ++i)
        #pragma unroll
        for (int j = 0; j < 4; ++j)
            #pragma unroll
            for (int c = 0; c < 4; ++c) acc[i][j][c] = 0.f;

    auto stage = [&](int t, int sb) {
        const int k0 = t * BKi;
        const uint32_t sbase = base + sb * STAGE_B;
        #pragma unroll
        for (int l = 0; l < 8; ++l) {
            int idx = tid + l * 256;
            int p = idx >> 10, cid = idx & 1023;
            int r = cid >> 3, s = cid & 7;
            uint32_t dst = sbase + p * PLANE_B + chunk_off8(s, r);
            if (p == 0) {
                int gr = row0 + r, ok = (gr < M1);
                cp16p(dst, Ah + (size_t)(ok ? gr : 0) * K + k0 + s * 8, ok ? 16 : 0);
            } else {
                cp16(dst, Bh + (size_t)(col0 + r) * K + k0 + s * 8);
            }
        }
    };

    stage(0, 0); CPCOMMIT();
    stage(1, 1); CPCOMMIT();

    const int a_r = lane & 15, a_s = lane >> 4;
    const int b_r = lane & 7,  b_s = (lane >> 3) & 1;

    for (int t = 0; t < nk; ++t) {
        cpwait(min(nk - 1 - t, 1));
        __syncthreads();
        const uint32_t pb = base + (t % NSTAGE) * STAGE_B;
        #pragma unroll
        for (int ks = 0; ks < 4; ++ks) {
            uint32_t af[4][4], bf[4][2];
            #pragma unroll
            for (int ni = 0; ni < 4; ++ni)
                ldm2(bf[ni], pb + PLANE_B + chunk_off8(2 * ks + b_s, wn + ni * 8 + b_r));
            #pragma unroll
            for (int mi = 0; mi < 4; ++mi)
                ldm4(af[mi], pb + chunk_off8(2 * ks + a_s, wm + mi * 16 + a_r));
            #pragma unroll
            for (int mi = 0; mi < 4; ++mi)
                #pragma unroll
                for (int ni = 0; ni < 4; ++ni)
                    mma16816(acc[mi][ni], af[mi], bf[ni]);
        }
        if (t + 2 < nk) { stage(t + 2, (t + 2) % NSTAGE); CPCOMMIT(); }
    }

    const int er = lane >> 2, ec = 2 * (lane & 3);
    const int part = col0 / DIMv;              // tile entirely in one part

    if (part < 2) {
        // ---- fused RoPE epilogue (unchanged from R8) ----
        __half* dstbase = (part == 0) ? qh : kh;
        int rb[8], rn[8];
        #pragma unroll
        for (int mi = 0; mi < 4; ++mi) {
            int gr = row0 + wm + mi * 16 + er;
            rb[2 * mi] = gr / Nv; rn[2 * mi] = gr - rb[2 * mi] * Nv;
            gr += 8;
            rb[2 * mi + 1] = gr / Nv; rn[2 * mi + 1] = gr - rb[2 * mi + 1] * Nv;
        }
        #pragma unroll
        for (int mi = 0; mi < 4; ++mi)
            #pragma unroll
            for (int ni = 0; ni < 4; ++ni) {
                int gc = col0 + wn + ni * 8 + ec;
                int rem = gc - part * DIMv;
                int h = rem >> 6, d = rem & 63, i = d >> 1;
                #pragma unroll
                for (int hf = 0; hf < 2; ++hf) {
                    int gr = row0 + wm + mi * 16 + er + 8 * hf;
                    if (gr >= M1) continue;
                    int b = rb[2 * mi + hf], n = rn[2 * mi + hf];
                    float v0 = acc[mi][ni][2 * hf], v1 = acc[mi][ni][2 * hf + 1];
                    if (n > 0) {
                        float c = __ldg(&fcos[(size_t)(n - 1) * 32 + i]);
                        float s = __ldg(&fsin[(size_t)(n - 1) * 32 + i]);
                        float t0 = v0 * c - v1 * s;
                        v1 = v0 * s + v1 * c;
                        v0 = t0;
                    }
                    *reinterpret_cast<__half2*>(
                        &dstbase[(((size_t)b * Hv + h) * Nv + n) * Dv + d]) =
                        __floats2half2_rn(v0, v1);
                }
            }
    } else {
        // ---- v-part: transpose in smem, write vt (bh,d,n) directly ----
        __syncthreads();                       // mainloop smem dead; reuse
        __half* sm = reinterpret_cast<__half*>(dsm);   // [col][136] layout
        #pragma unroll
        for (int mi = 0; mi < 4; ++mi)
            #pragma unroll
            for (int ni = 0; ni < 4; ++ni) {
                int row = wm + mi * 16 + er, col = wn + ni * 8 + ec;
                sm[(col)     * 136 + row    ] = __float2half_rn(acc[mi][ni][0]);
                sm[(col + 1) * 136 + row    ] = __float2half_rn(acc[mi][ni][1]);
                sm[(col)     * 136 + row + 8] = __float2half_rn(acc[mi][ni][2]);
                sm[(col + 1) * 136 + row + 8] = __float2half_rn(acc[mi][ni][3]);
            }
        __syncthreads();

        const int hbase = (col0 - 2 * DIMv) >> 6;      // even head index base
        const int bb = row0 / Nv;
        const int bound = (bb + 1) * Nv;
        #pragma unroll
        for (int it = 0; it < 16; ++it) {
            int j = warp * 16 + it;                    // local col (d within 2 heads)
            int h = hbase + (j >> 6), d = j & 63;
            // lane covers tokens row0 + 4*lane .. +4
            uint2 v4 = *reinterpret_cast<const uint2*>(&sm[j * 136 + lane * 4]);
            const __half* hv = reinterpret_cast<const __half*>(&v4);
            #pragma unroll
            for (int i = 0; i < 4; ++i) {
                int gr = row0 + lane * 4 + i;
                if (gr < M1) {
                    int b = (gr >= bound) ? bb + 1 : bb;
                    int n = gr - b * Nv;
                    vt[((size_t)(b * Hv + h) * 72 + d) * NP + n] = hv[i];
                }
            }
        }
    }
}

// ============================================================================
// GEMM2 (generic, R8-frozen): C = A @ B^T + bias, fp32 out.
// ============================================================================
__global__ __launch_bounds__(256, 2)
void gemm_out(const __half* __restrict__ Ah, const __half* __restrict__ Bh,
              const float* __restrict__ bias, float* __restrict__ C,
              int M, int Nc, int K) {
    extern __shared__ char dsm[];
    const uint32_t base = s2u(dsm);
    const int tid  = threadIdx.x;
    const int warp = tid >> 5, lane = tid & 31;
    const int row0 = blockIdx.y * 128, col0 = blockIdx.x * 128;
    const int wm = (warp >> 2) * 64, wn = (warp & 3) * 32;
    const int nk = K / BKi;

    float acc[4][4][4];
    #pragma unroll
    for (int i = 0; i < 4; ++i)
        #pragma unroll
        for (int j = 0; j < 4; ++j)
            #pragma unroll
            for (int c = 0; c < 4; ++c) acc[i][j][c] = 0.f;

    auto stage = [&](int t, int sb) {
        const int k0 = t * BKi;
        const uint32_t sbase = base + sb * STAGE_B;
        #pragma unroll
        for (int l = 0; l < 8; ++l) {
            int idx = tid + l * 256;
            int p = idx >> 10, cid = idx & 1023;
            int r = cid >> 3, s = cid & 7;
            uint32_t dst = sbase + p * PLANE_B + chunk_off8(s, r);
            if (p == 0) {
                int gr = row0 + r, ok = (gr < M);
                cp16p(dst, Ah + (size_t)(ok ? gr : 0) * K + k0 + s * 8, ok ? 16 : 0);
            } else {
                cp16(dst, Bh + (size_t)(col0 + r) * K + k0 + s * 8);
            }
        }
    };

    stage(0, 0); CPCOMMIT();
    stage(1, 1); CPCOMMIT();

    const int a_r = lane & 15, a_s = lane >> 4;
    const int b_r = lane & 7,  b_s = (lane >> 3) & 1;

    for (int t = 0; t < nk; ++t) {
        cpwait(min(nk - 1 - t, 1));
        __syncthreads();
        const uint32_t pb = base + (t % NSTAGE) * STAGE_B;
        #pragma unroll
        for (int ks = 0; ks < 4; ++ks) {
            uint32_t af[4][4], bf[4][2];
            #pragma unroll
            for (int ni = 0; ni < 4; ++ni)
                ldm2(bf[ni], pb + PLANE_B + chunk_off8(2 * ks + b_s, wn + ni * 8 + b_r));
            #pragma unroll
            for (int mi = 0; mi < 4; ++mi)
                ldm4(af[mi], pb + chunk_off8(2 * ks + a_s, wm + mi * 16 + a_r));
            #pragma unroll
            for (int mi = 0; mi < 4; ++mi)
                #pragma unroll
                for (int ni = 0; ni < 4; ++ni)
                    mma16816(acc[mi][ni], af[mi], bf[ni]);
        }
        if (t + 2 < nk) { stage(t + 2, (t + 2) % NSTAGE); CPCOMMIT(); }
    }

    const int er = lane >> 2, ec = 2 * (lane & 3);
    #pragma unroll
    for (int mi = 0; mi < 4; ++mi)
        #pragma unroll
        for (int ni = 0; ni < 4; ++ni) {
            int gc = col0 + wn + ni * 8 + ec;
            float b0 = bias[gc], b1 = bias[gc + 1];
            int gr0 = row0 + wm + mi * 16 + er;
            if (gr0 < M)
                *reinterpret_cast<float2*>(&C[(size_t)gr0 * Nc + gc]) =
                    make_float2(acc[mi][ni][0] + b0, acc[mi][ni][1] + b1);
            if (gr0 + 8 < M)
                *reinterpret_cast<float2*>(&C[(size_t)(gr0 + 8) * Nc + gc]) =
                    make_float2(acc[mi][ni][2] + b0, acc[mi][ni][3] + b1);
        }
}

// ============================================================================
// feature GEMM: F = relu(X @ projS^T) + 1e-6
// grid (9, 384, 2): z=0 -> qf (n,j); z=1 -> kfT (j,n)
// ============================================================================
__global__ __launch_bounds__(256)
void feat_gemm(const __half* __restrict__ qh, const __half* __restrict__ kh,
               const __half* __restrict__ projS,
               __half* __restrict__ qf, __half* __restrict__ kft) {
    __shared__ char fsm[24576];
    const uint32_t base = s2u(fsm), bB = base + 16384;
    const int tid = threadIdx.x, warp = tid >> 5, lane = tid & 31;
    const int n0 = blockIdx.x * 128, bh = blockIdx.y, qk = blockIdx.z;
    const __half* A = (qk ? kh : qh) + (size_t)bh * Nv * Dv;

    #pragma unroll
    for (int l = 0; l < 4; ++l) {
        int idx = tid + l * 256;
        int r = idx >> 3, s = idx & 7;
        int n = n0 + r, ok = (n < Nv);
        cp16p(base + chunk_off(s, r), A + (size_t)(ok ? n : 0) * Dv + s * 8, ok ? 16 : 0);
    }
    #pragma unroll
    for (int l = 0; l < 2; ++l) {
        int idx = tid + l * 256;
        int r = idx >> 3, s = idx & 7;
        cp16(bB + chunk_off64(s, r), projS + (size_t)r * Dv + s * 8);
    }
    CPCOMMIT(); cpwait(0); __syncthreads();

    const int wm = (warp >> 1) * 32, wn = (warp & 1) * 32;
    const int a_r = lane & 15, a_s = lane >> 4;
    const int b_r = lane & 7,  b_s = (lane >> 3) & 1;
    float acc[2][4][4];
    #pragma unroll
    for (int i = 0; i < 2; ++i)
        #pragma unroll
        for (int j = 0; j < 4; ++j)
            #pragma unroll
            for (int c = 0; c < 4; ++c) acc[i][j][c] = 0.f;

    #pragma unroll
    for (int ks = 0; ks < 4; ++ks) {
        uint32_t af[2][4], bf[4][2];
        #pragma unroll
        for (int ni = 0; ni < 4; ++ni)
            ldm2(bf[ni], bB + chunk_off64(2 * ks + b_s, wn + ni * 8 + b_r));
        #pragma unroll
        for (int mi = 0; mi < 2; ++mi)
            ldm4(af[mi], base + chunk_off(2 * ks + a_s, wm + mi * 16 + a_r));
        #pragma unroll
        for (int mi = 0; mi < 2; ++mi)
            #pragma unroll
            for (int ni = 0; ni < 4; ++ni)
                mma16816(acc[mi][ni], af[mi], bf[ni]);
    }

    const int er = lane >> 2, ec = 2 * (lane & 3);
    if (qk == 0) {
        #pragma unroll
        for (int mi = 0; mi < 2; ++mi)
            #pragma unroll
            for (int ni = 0; ni < 4; ++ni) {
                int row = wm + mi * 16 + er, col = wn + ni * 8 + ec;
                int n = n0 + row;
                if (n < Nv) {
                    float v0 = fmaxf(acc[mi][ni][0], 0.f) + 1e-6f;
                    float v1 = fmaxf(acc[mi][ni][1], 0.f) + 1e-6f;
                    *reinterpret_cast<__half2*>(
                        &qf[((size_t)bh * Nv + n) * Dv + col]) = __floats2half2_rn(v0, v1);
                }
                if (n + 8 < Nv) {
                    float v2 = fmaxf(acc[mi][ni][2], 0.f) + 1e-6f;
                    float v3 = fmaxf(acc[mi][ni][3], 0.f) + 1e-6f;
                    *reinterpret_cast<__half2*>(
                        &qf[((size_t)bh * Nv + n + 8) * Dv + col]) = __floats2half2_rn(v2, v3);
                }
            }
    } else {
        __syncthreads();
        __half* sm16 = reinterpret_cast<__half*>(fsm);
        #pragma unroll
        for (int mi = 0; mi < 2; ++mi)
            #pragma unroll
            for (int ni = 0; ni < 4; ++ni) {
                int row = wm + mi * 16 + er, col = wn + ni * 8 + ec;
                sm16[(col)     * 136 + row    ] = __float2half_rn(fmaxf(acc[mi][ni][0], 0.f) + 1e-6f);
                sm16[(col + 1) * 136 + row    ] = __float2half_rn(fmaxf(acc[mi][ni][1], 0.f) + 1e-6f);
                sm16[(col)     * 136 + row + 8] = __float2half_rn(fmaxf(acc[mi][ni][2], 0.f) + 1e-6f);
                sm16[(col + 1) * 136 + row + 8] = __float2half_rn(fmaxf(acc[mi][ni][3], 0.f) + 1e-6f);
            }
        __syncthreads();
        int j = tid >> 2, seg = (tid & 3) * 32;
        __half* dst = &kft[(size_t)bh * Dv * NP + (size_t)j * NP + n0 + seg];
        #pragma unroll
        for (int i = 0; i < 32; i += 2) {
            int n = n0 + seg + i;
            if (n + 1 < Nv)
                *reinterpret_cast<__half2*>(dst + i) =
                    *reinterpret_cast<const __half2*>(&sm16[j * 136 + seg + i]);
            else if (n < Nv)
                dst[i] = sm16[j * 136 + seg + i];
        }
    }
}

// ============================================================================
// ctx GEMM: C[r][d] = sum_n vt[r,n]*kfT[d,n]; row 64 = ksum.
// ============================================================================
#define CSTG_B 12288
__global__ __launch_bounds__(256)
void ctx_gemm(const __half* __restrict__ vt, const __half* __restrict__ kft,
              __half* __restrict__ ctxh) {
    __shared__ char csm[4 * CSTG_B];
    const uint32_t base = s2u(csm);
    const int tid = threadIdx.x, warp = tid >> 5, lane = tid & 31;
    const int bh = blockIdx.x;
    const __half* Av = vt  + (size_t)bh * 72 * NP;
    const __half* Bk = kft + (size_t)bh * Dv * NP;
    const int nk = NP / 32;

    auto stage = [&](int t, int sb) {
        const int k0 = t * 32;
        const uint32_t sbase = base + sb * CSTG_B;
        #pragma unroll
        for (int l = 0; l < 3; ++l) {
            int idx = tid + l * 256;
            if (idx < 512) {
                int r = idx >> 2, s = idx & 3;
                int ok = (r < 72);
                cp16p(sbase + chunk_off(s, r),
                      Av + (size_t)(ok ? r : 0) * NP + k0 + s * 8, ok ? 16 : 0);
            } else {
                int j = idx - 512;
                int r = j >> 2, s = j & 3;
                cp16(sbase + 8192 + chunk_off64(s, r),
                     Bk + (size_t)r * NP + k0 + s * 8);
            }
        }
    };

    stage(0, 0); CPCOMMIT();
    stage(1, 1); CPCOMMIT();
    stage(2, 2); CPCOMMIT();

    const int wm = (warp >> 1) * 32, wn = (warp & 1) * 32;
    const int a_r = lane & 15, a_s = lane >> 4;
    const int b_r = lane & 7,  b_s = (lane >> 3) & 1;
    float acc[2][4][4];
    #pragma unroll
    for (int i = 0; i < 2; ++i)
        #pragma unroll
        for (int j = 0; j < 4; ++j)
            #pragma unroll
            for (int c = 0; c < 4; ++c) acc[i][j][c] = 0.f;

    for (int t = 0; t < nk; ++t) {
        cpwait(min(nk - 1 - t, 2));
        __syncthreads();
        const uint32_t pb = base + (t & 3) * CSTG_B;
        #pragma unroll
        for (int ks = 0; ks < 2; ++ks) {
            uint32_t af[2][4], bf[4][2];
            #pragma unroll
            for (int ni = 0; ni < 4; ++ni)
                ldm2(bf[ni], pb + 8192 + chunk_off64(2 * ks + b_s, wn + ni * 8 + b_r));
            #pragma unroll
            for (int mi = 0; mi < 2; ++mi)
                ldm4(af[mi], pb + chunk_off(2 * ks + a_s, wm + mi * 16 + a_r));
            #pragma unroll
            for (int mi = 0; mi < 2; ++mi)
                #pragma unroll
                for (int ni = 0; ni < 4; ++ni)
                    mma16816(acc[mi][ni], af[mi], bf[ni]);
        }
        __syncthreads();
        if (t + 3 < nk) { stage(t + 3, (t + 3) & 3); CPCOMMIT(); }
    }

    const int er = lane >> 2, ec = 2 * (lane & 3);
    #pragma unroll
    for (int mi = 0; mi < 2; ++mi)
        #pragma unroll
        for (int ni = 0; ni < 4; ++ni) {
            int row = wm + mi * 16 + er, col = wn + ni * 8 + ec;
            if (row < 72)
                *reinterpret_cast<__half2*>(&ctxh[(size_t)bh * 128 * Dv + row * Dv + col]) =
                    __floats2half2_rn(acc[mi][ni][0], acc[mi][ni][1]);
            if (row + 8 < 72)
                *reinterpret_cast<__half2*>(&ctxh[(size_t)bh * 128 * Dv + (row + 8) * Dv + col]) =
                    __floats2half2_rn(acc[mi][ni][2], acc[mi][ni][3]);
        }
}

// ============================================================================
// out GEMM: col64 = denom; divide in epilogue -> ah fp16
// ============================================================================
__global__ __launch_bounds__(256)
void out_gemm(const __half* __restrict__ qf, const __half* __restrict__ ctxh,
              __half* __restrict__ ah) {
    __shared__ char osm[32768];
    __shared__ float sden[128];
    const uint32_t base = s2u(osm), bB = base + 16384;
    const int tid = threadIdx.x, warp = tid >> 5, lane = tid & 31;
    const int n0 = blockIdx.x * 128, bh = blockIdx.y;
    const int b = bh / Hv, h = bh % Hv;
    const __half* A = qf   + (size_t)bh * Nv * Dv;
    const __half* Bm = ctxh + (size_t)bh * 128 * Dv;

    #pragma unroll
    for (int l = 0; l < 4; ++l) {
        int idx = tid + l * 256;
        int r = idx >> 3, s = idx & 7;
        int n = n0 + r, ok = (n < Nv);
        cp16p(base + chunk_off(s, r), A + (size_t)(ok ? n : 0) * Dv + s * 8, ok ? 16 : 0);
    }
    #pragma unroll
    for (int l = 0; l < 4; ++l) {
        int idx = tid + l * 256;
        int r = idx >> 3, s = idx & 7;
        cp16(bB + chunk_off(s, r), Bm + (size_t)r * Dv + s * 8);
    }
    CPCOMMIT(); cpwait(0); __syncthreads();

    const int wm = (warp >> 2) * 64, wn = (warp & 3) * 32;
    const int a_r = lane & 15, a_s = lane >> 4;
    const int b_r = lane & 7,  b_s = (lane >> 3) & 1;
    float acc[4][4][4];
    #pragma unroll
    for (int i = 0; i < 4; ++i)
        #pragma unroll
        for (int j = 0; j < 4; ++j)
            #pragma unroll
            for (int c = 0; c < 4; ++c) acc[i][j][c] = 0.f;

    #pragma unroll
    for (int ks = 0; ks < 4; ++ks) {
        uint32_t af[4][4], bf[4][2];
        #pragma unroll
        for (int ni = 0; ni < 4; ++ni)
            ldm2(bf[ni], bB + chunk_off(2 * ks + b_s, wn + ni * 8 + b_r));
        #pragma unroll
        for (int mi = 0; mi < 4; ++mi)
            ldm4(af[mi], base + chunk_off(2 * ks + a_s, wm + mi * 16 + a_r));
        #pragma unroll
        for (int mi = 0; mi < 4; ++mi)
            #pragma unroll
            for (int ni = 0; ni < 4; ++ni)
                mma16816(acc[mi][ni], af[mi], bf[ni]);
    }

    const int er = lane >> 2, ec = 2 * (lane & 3);
    if (wn == 64 && (lane & 3) == 0) {
        #pragma unroll
        for (int mi = 0; mi < 4; ++mi) {
            sden[wm + mi * 16 + er]     = acc[mi][0][0];
            sden[wm + mi * 16 + er + 8] = acc[mi][0][2];
        }
    }
    __syncthreads();
    if (wn < 64) {
        #pragma unroll
        for (int mi = 0; mi < 4; ++mi)
            #pragma unroll
            for (int ni = 0; ni < 4; ++ni) {
                int row = wm + mi * 16 + er, col = wn + ni * 8 + ec;
                int n = n0 + row;
                if (n < Nv) {
                    float inv = 1.f / sden[row];
                    *reinterpret_cast<__half2*>(
                        &ah[((size_t)(b * Nv + n)) * DIMv + h * Dv + col]) =
                        __floats2half2_rn(acc[mi][ni][0] * inv, acc[mi][ni][1] * inv);
                }
                if (n + 8 < Nv) {
                    float inv = 1.f / sden[row + 8];
                    *reinterpret_cast<__half2*>(
                        &ah[((size_t)(b * Nv + n + 8)) * DIMv + h * Dv + col]) =
                        __floats2half2_rn(acc[mi][ni][2] * inv, acc[mi][ni][3] * inv);
                }
            }
    }
}

// ============================================================================
// launcher
// ============================================================================
extern "C" void kernel_launch(void* const* d_in, const int* in_sizes, int n_in,
                              void* d_out, int out_size) {
    const float* x     = (const float*)d_in[0];
    const float* W_qkv = (const float*)d_in[1];
    const float* W_out = (const float*)d_in[2];
    const float* b_out = (const float*)d_in[3];
    const float* proj  = (const float*)d_in[4];
    const float* fcos  = (const float*)d_in[5];
    const float* fsin  = (const float*)d_in[6];
    float* out = (float*)d_out;

    __half *xh, *wqh, *woh, *projh, *qh, *kh, *vt, *qfh, *kft, *ctxh, *ah;
    cudaGetSymbolAddress((void**)&xh,    g_xh);
    cudaGetSymbolAddress((void**)&wqh,   g_wqh);
    cudaGetSymbolAddress((void**)&woh,   g_woh);
    cudaGetSymbolAddress((void**)&projh, g_projh);
    cudaGetSymbolAddress((void**)&qh,    g_qh);
    cudaGetSymbolAddress((void**)&kh,    g_kh);
    cudaGetSymbolAddress((void**)&vt,    g_vt);
    cudaGetSymbolAddress((void**)&qfh,   g_qfh);
    cudaGetSymbolAddress((void**)&kft,   g_kft);
    cudaGetSymbolAddress((void**)&ctxh,  g_ctxh);
    cudaGetSymbolAddress((void**)&ah,    g_ah);

    cudaFuncSetAttribute(gemm_qkv,
                         cudaFuncAttributeMaxDynamicSharedMemorySize, GSMEM);
    cudaFuncSetAttribute(gemm_out,
                         cudaFuncAttributeMaxDynamicSharedMemorySize, GSMEM);

    // 0) conversions (+ vt ones rows)
    conv_fp16<<<2048, 256>>>(x,     xh,  (size_t)M1 * DIMv / 4);
    conv_fp16<<<512,  256>>>(W_qkv, wqh, (size_t)G3 * DIMv / 4);
    conv_fp16<<<256,  256>>>(W_out, woh, (size_t)DIMv * DIMv / 4);
    conv_misc<<<(Dv * Dv + BH * Nv + 255) / 256, 256>>>(proj, projh, vt);

    // 1) QKV projection: fused RoPE (q,k) + fused v-transpose -> qh, kh, vt
    {
        dim3 grid(G3 / 128, (M1 + 127) / 128);
        gemm_qkv<<<grid, 256, GSMEM>>>(xh, wqh, fcos, fsin, qh, kh, vt);
    }
    // 2) feature maps (HMMA)
    {
        dim3 grid(9, BH, 2);
        feat_gemm<<<grid, 256>>>(qh, kh, projh, qfh, kft);
    }
    // 3) context + ksum (HMMA, ones-row trick)
    ctx_gemm<<<BH, 256>>>(vt, kft, ctxh);
    // 4) output contraction + divide -> ah fp16
    {
        dim3 grid(9, BH);
        out_gemm<<<grid, 256>>>(qfh, ctxh, ah);
    }
    // 5) output projection + bias
    {
        dim3 grid(DIMv / 128, (M1 + 127) / 128);
        gemm_out<<<grid, 256, GSMEM>>>(ah, woh, b_out, out, M1, DIMv, DIMv);
    }
}